// round 15
// baseline (speedup 1.0000x reference)
#include <cuda_runtime.h>
#include <cuda_bf16.h>
#include <cstdint>

// Math (first-order collapse of 19 gradient steps, validated):
//   a0    = x @ phi
//   resid = a0 @ phi^T - x
//   out   = a0 - C19 * (resid @ phi + sm * sign(a0)),  C19 = 19*0.005/256
//
// R15: kernels are cp.async ISSUE-bound (~1.1 op/cyc/SM across R7/R9/R13
// configs). Halve the op count with BM=BN=128 tiles (traffic halves).
// CTA split-K (z) only to fill the grid; fp32 partials + combine kernels.
// GEMM1 accuracy: bf16 hi/lo split via K-concat (K=9216):
//   A1 = [xh | xh | xl],  B1 = [phT | plT | phT]  ->  xh*ph + xh*pl + xl*ph

#define DINL __device__ __forceinline__

// ---------------- scratch (device globals; no allocation allowed) -----------
__device__ __align__(1024) __nv_bfloat16 g_A1[256 * 9216];   // 4.7 MB
__device__ __align__(1024) __nv_bfloat16 g_B1[4096 * 9216];  // 75.5 MB
__device__ __align__(1024) __nv_bfloat16 g_B2[3072 * 4096];  // 25.2 MB
__device__ __align__(1024) float         g_a0f[256 * 4096];  // 4.2 MB
__device__ __align__(1024) __nv_bfloat16 g_a0h[256 * 4096];  // 2.1 MB
__device__ __align__(1024) __nv_bfloat16 g_rh[256 * 3072];   // 1.6 MB
__device__ __align__(1024) float         g_part[4 * 256 * 4096];  // 16.8 MB

// ---------------- PTX helpers -----------------------------------------------
DINL uint32_t smem_u32(const void* p) {
    uint32_t a;
    asm("{ .reg .u64 t; cvta.to.shared.u64 t, %1; cvt.u32.u64 %0, t; }"
        : "=r"(a) : "l"(p));
    return a;
}

#define CP16(dst, src) \
    asm volatile("cp.async.cg.shared.global [%0], [%1], 16;" :: "r"(dst), "l"(src) : "memory")
#define CP_COMMIT() asm volatile("cp.async.commit_group;" ::: "memory")
#define CP_WAIT1()  asm volatile("cp.async.wait_group 1;" ::: "memory")
#define CP_WAIT0()  asm volatile("cp.async.wait_group 0;" ::: "memory")

#define LDSM4(r0, r1, r2, r3, addr) \
    asm volatile("ldmatrix.sync.aligned.m8n8.x4.shared.b16 {%0,%1,%2,%3}, [%4];" \
        : "=r"(r0), "=r"(r1), "=r"(r2), "=r"(r3) : "r"(addr))

DINL void mma16(float& d0, float& d1, float& d2, float& d3,
                uint32_t a0, uint32_t a1, uint32_t a2, uint32_t a3,
                uint32_t b0, uint32_t b1) {
    asm volatile(
        "mma.sync.aligned.m16n8k16.row.col.f32.bf16.bf16.f32 "
        "{%0,%1,%2,%3}, {%4,%5,%6,%7}, {%8,%9}, {%0,%1,%2,%3};"
        : "+f"(d0), "+f"(d1), "+f"(d2), "+f"(d3)
        : "r"(a0), "r"(a1), "r"(a2), "r"(a3), "r"(b0), "r"(b1));
}

DINL uint32_t pack2(float a, float b) {
    __nv_bfloat162 t = __floats2bfloat162_rn(a, b);
    return *reinterpret_cast<uint32_t*>(&t);
}

// ---------------- conversion kernels -----------------------------------------
__global__ __launch_bounds__(256) void conv_x(const float* __restrict__ x,
                                              __nv_bfloat16* __restrict__ A1) {
    int t = blockIdx.x * 256 + threadIdx.x;  // 256*3072 elements
    int m = t / 3072;
    int k = t - m * 3072;
    float f = x[t];
    __nv_bfloat16 h = __float2bfloat16(f);
    __nv_bfloat16 l = __float2bfloat16(f - __bfloat162float(h));
    size_t base = (size_t)m * 9216 + k;
    A1[base] = h;          // pairs with phT
    A1[base + 3072] = h;   // pairs with plT
    A1[base + 6144] = l;   // pairs with phT
}

// tile: 64 pixels (p) x 32 neurons (n), 512 threads
__global__ __launch_bounds__(512) void conv_phi(const float* __restrict__ phi,
                                                __nv_bfloat16* __restrict__ B1,
                                                __nv_bfloat16* __restrict__ B2) {
    __shared__ float tile[64][33];
    int p0 = blockIdx.y * 64, n0 = blockIdx.x * 32;
    int tx = threadIdx.x & 31, ty = threadIdx.x >> 5;  // ty 0..15
#pragma unroll
    for (int r = 0; r < 4; r++) {
        int pl = ty + 16 * r;
        float f = phi[(size_t)(p0 + pl) * 4096 + n0 + tx];
        tile[pl][tx] = f;
        B2[(size_t)(p0 + pl) * 4096 + n0 + tx] = __float2bfloat16(f);
    }
    __syncthreads();
    int pl2 = threadIdx.x & 63, nl2 = threadIdx.x >> 6;  // nl2 0..7
#pragma unroll
    for (int r = 0; r < 4; r++) {
        int nl = nl2 + 8 * r;
        float f = tile[pl2][nl];
        __nv_bfloat16 h = __float2bfloat16(f);
        __nv_bfloat16 l = __float2bfloat16(f - __bfloat162float(h));
        size_t base = (size_t)(n0 + nl) * 9216 + p0 + pl2;
        B1[base] = h;          // phT
        B1[base + 3072] = l;   // plT
        B1[base + 6144] = h;   // phT (pairs with xl)
    }
}

// ---------------- bf16 tensor-core GEMM (split-K partial) --------------------
// P[z] = A[m, zK:(z+1)K] * B[n, ...]^T.  BM=128, BN=128, BK=32.
// 256 threads = 8 warps (2M x 4N); warp tile 64x32 = 4 m16 x 4 n8.
// 2-stage cp.async double buffer (R12-validated group discipline).
// Static smem 40,960 B.

constexpr int SAu = 20;              // u32 row stride (16 data + 4 pad)
constexpr int STG = 128 * SAu;       // 2560 u32 per operand per stage

__global__ __launch_bounds__(256) void gemm_part(
    const __nv_bfloat16* __restrict__ A, const __nv_bfloat16* __restrict__ B,
    float* __restrict__ P, int Kper, int lda, int ldb, int ldc, int MN)
{
    __shared__ uint32_t As[2 * STG];
    __shared__ uint32_t Bs[2 * STG];
    const uint32_t sA_u = smem_u32(As);
    const uint32_t sB_u = smem_u32(Bs);

    const int tid = threadIdx.x, lane = tid & 31, wid = tid >> 5;
    const int wm = wid >> 2, wn = wid & 3;     // 2(M) x 4(N)
    const int m0 = blockIdx.y * 128, n0 = blockIdx.x * 128;
    const int z = blockIdx.z;
    const int g = lane >> 2, c4 = lane & 3;

    A += (size_t)z * Kper;   // K contiguous in both operands
    B += (size_t)z * Kper;

    // ldmatrix lane offsets (bytes)
    const int j = lane >> 3, r8 = lane & 7;
    const uint32_t aoffB = (uint32_t)(((j & 1) * 8 + r8) * SAu + (j >> 1) * 4) * 4;
    const uint32_t boffB = (uint32_t)(r8 * SAu + (j & 1) * 4 + (j >> 1) * 8) * 4;

    float acc[4][4][4];
#pragma unroll
    for (int mt = 0; mt < 4; mt++)
#pragma unroll
        for (int nt = 0; nt < 4; nt++)
#pragma unroll
            for (int r = 0; r < 4; r++) acc[mt][nt][r] = 0.0f;

    const int nk = Kper >> 5;   // BK = 32

    auto load_tile = [&](int t, int slot) {
        // A: 128 rows x 64 B = 512 x 16B; 2 per thread
        const char* Ab = (const char*)A + ((size_t)m0 * lda + t * 32) * 2;
        uint32_t ad = sA_u + slot * STG * 4;
#pragma unroll
        for (int h = 0; h < 2; h++) {
            int idx = tid + h * 256;
            int row = idx >> 2, seg = idx & 3;
            CP16(ad + (uint32_t)(row * SAu + seg * 4) * 4,
                 Ab + (size_t)row * lda * 2 + seg * 16);
        }
        // B: 128 rows x 64 B; 2 per thread
        const char* Bb = (const char*)B + ((size_t)n0 * ldb + t * 32) * 2;
        uint32_t bd = sB_u + slot * STG * 4;
#pragma unroll
        for (int h = 0; h < 2; h++) {
            int idx = tid + h * 256;
            int row = idx >> 2, seg = idx & 3;
            CP16(bd + (uint32_t)(row * SAu + seg * 4) * 4,
                 Bb + (size_t)row * ldb * 2 + seg * 16);
        }
    };

    load_tile(0, 0);
    CP_COMMIT();

    for (int i = 0; i < nk; i++) {
        if (i + 1 < nk) {
            load_tile(i + 1, (i + 1) & 1);
            CP_COMMIT();
            CP_WAIT1();       // tile i resident
        } else {
            CP_WAIT0();       // final tile: drain (R12 race fix)
        }
        __syncthreads();

        const uint32_t aBase = sA_u + ((i & 1) * STG + (wm * 64) * SAu) * 4 + aoffB;
        const uint32_t bBase = sB_u + ((i & 1) * STG + (wn * 32) * SAu) * 4 + boffB;

        // B fragments: 4 LDSM.x4 (each covers both k16 steps)
        uint32_t bb[4][2][2];   // [nt][ks][2]
#pragma unroll
        for (int nt = 0; nt < 4; nt++) {
            uint32_t ba = bBase + (uint32_t)(nt * 8 * SAu) * 4;
            LDSM4(bb[nt][0][0], bb[nt][0][1], bb[nt][1][0], bb[nt][1][1], ba);
        }
#pragma unroll
        for (int ks = 0; ks < 2; ks++) {
            uint32_t aa[4][4];
#pragma unroll
            for (int mt = 0; mt < 4; mt++) {
                uint32_t aaddr = aBase + (uint32_t)(mt * 16 * SAu + ks * 8) * 4;
                LDSM4(aa[mt][0], aa[mt][1], aa[mt][2], aa[mt][3], aaddr);
            }
#pragma unroll
            for (int mt = 0; mt < 4; mt++)
#pragma unroll
                for (int nt = 0; nt < 4; nt++)
                    mma16(acc[mt][nt][0], acc[mt][nt][1], acc[mt][nt][2], acc[mt][nt][3],
                          aa[mt][0], aa[mt][1], aa[mt][2], aa[mt][3],
                          bb[nt][ks][0], bb[nt][ks][1]);
        }
        __syncthreads();
    }

    // ---- write fp32 partial ----
    float* Pz = P + (size_t)z * MN;
#pragma unroll
    for (int mt = 0; mt < 4; mt++) {
        const int r0 = m0 + wm * 64 + mt * 16 + g;
#pragma unroll
        for (int nt = 0; nt < 4; nt++) {
            const int col = n0 + wn * 32 + nt * 8 + 2 * c4;
#pragma unroll
            for (int half = 0; half < 2; half++) {
                const int row = r0 + half * 8;
                float2 v = {acc[mt][nt][half * 2 + 0], acc[mt][nt][half * 2 + 1]};
                *reinterpret_cast<float2*>(&Pz[(size_t)row * ldc + col]) = v;
            }
        }
    }
}

// ---------------- combine kernels (sum_z P[z] + epilogue) --------------------
__global__ __launch_bounds__(256) void combine1(const float* __restrict__ P,
                                                float* __restrict__ a0f,
                                                __nv_bfloat16* __restrict__ a0h,
                                                int MN, int NZ) {
    int i = blockIdx.x * 256 + threadIdx.x;
    float4 s = reinterpret_cast<const float4*>(P)[i];
    for (int zz = 1; zz < NZ; zz++) {
        float4 p = reinterpret_cast<const float4*>(P + (size_t)zz * MN)[i];
        s.x += p.x; s.y += p.y; s.z += p.z; s.w += p.w;
    }
    reinterpret_cast<float4*>(a0f)[i] = s;
    uint2 pk = {pack2(s.x, s.y), pack2(s.z, s.w)};
    reinterpret_cast<uint2*>(a0h)[i] = pk;
}

__global__ __launch_bounds__(256) void combine2(const float* __restrict__ P,
                                                const float* __restrict__ x,
                                                __nv_bfloat16* __restrict__ rh,
                                                int MN, int NZ) {
    int i = blockIdx.x * 256 + threadIdx.x;
    float4 s = reinterpret_cast<const float4*>(P)[i];
    for (int zz = 1; zz < NZ; zz++) {
        float4 p = reinterpret_cast<const float4*>(P + (size_t)zz * MN)[i];
        s.x += p.x; s.y += p.y; s.z += p.z; s.w += p.w;
    }
    const float4 xv = reinterpret_cast<const float4*>(x)[i];
    uint2 pk = {pack2(s.x - xv.x, s.y - xv.y), pack2(s.z - xv.z, s.w - xv.w)};
    reinterpret_cast<uint2*>(rh)[i] = pk;
}

__global__ __launch_bounds__(256) void combine3(const float* __restrict__ P,
                                                const float* __restrict__ a0f,
                                                const float* __restrict__ SMP,
                                                float* __restrict__ out,
                                                int MN, int NZ) {
    const float c19 = 19.0f * (0.005f / 256.0f);
    const float smv = SMP[0];
    int i = blockIdx.x * 256 + threadIdx.x;
    float4 s = reinterpret_cast<const float4*>(P)[i];
    for (int zz = 1; zz < NZ; zz++) {
        float4 p = reinterpret_cast<const float4*>(P + (size_t)zz * MN)[i];
        s.x += p.x; s.y += p.y; s.z += p.z; s.w += p.w;
    }
    const float4 av = reinterpret_cast<const float4*>(a0f)[i];
    float4 o;
    float s0 = (av.x > 0.f) ? 1.f : ((av.x < 0.f) ? -1.f : 0.f);
    float s1 = (av.y > 0.f) ? 1.f : ((av.y < 0.f) ? -1.f : 0.f);
    float s2 = (av.z > 0.f) ? 1.f : ((av.z < 0.f) ? -1.f : 0.f);
    float s3 = (av.w > 0.f) ? 1.f : ((av.w < 0.f) ? -1.f : 0.f);
    o.x = av.x - c19 * (s.x + smv * s0);
    o.y = av.y - c19 * (s.y + smv * s1);
    o.z = av.z - c19 * (s.z + smv * s2);
    o.w = av.w - c19 * (s.w + smv * s3);
    reinterpret_cast<float4*>(out)[i] = o;
}

// ---------------- launch -----------------------------------------------------
extern "C" void kernel_launch(void* const* d_in, const int* in_sizes, int n_in,
                              void* d_out, int out_size)
{
    const float* x   = (const float*)d_in[0];  // [256, 3072]
    const float* phi = (const float*)d_in[1];  // [3072, 4096]
    const float* smp = (const float*)d_in[2];  // scalar
    float* out = (float*)d_out;                // [256, 4096]

    __nv_bfloat16 *A1, *B1, *B2, *a0h, *rh;
    float *a0f, *part;
    cudaGetSymbolAddress((void**)&A1, g_A1);
    cudaGetSymbolAddress((void**)&B1, g_B1);
    cudaGetSymbolAddress((void**)&B2, g_B2);
    cudaGetSymbolAddress((void**)&a0f, g_a0f);
    cudaGetSymbolAddress((void**)&a0h, g_a0h);
    cudaGetSymbolAddress((void**)&rh, g_rh);
    cudaGetSymbolAddress((void**)&part, g_part);

    const int MN1 = 256 * 4096;
    const int MN2 = 256 * 3072;

    // conversions
    conv_x<<<(256 * 3072) / 256, 256>>>(x, A1);
    conv_phi<<<dim3(4096 / 32, 3072 / 64), 512>>>(phi, B1, B2);

    // GEMM1: a0 = A1 @ B1^T   M=256, N=4096, K=9216, z=3 (Kper=3072) -> 192 CTAs
    gemm_part<<<dim3(4096 / 128, 2, 3), 256>>>(
        A1, B1, part, 3072, 9216, 9216, 4096, MN1);
    combine1<<<MN1 / 1024, 256>>>(part, a0f, a0h, MN1, 3);

    // GEMM2: resid = a0h @ B2^T - x   M=256, N=3072, K=4096, z=4 (Kper=1024) -> 192 CTAs
    gemm_part<<<dim3(3072 / 128, 2, 4), 256>>>(
        a0h, B2, part, 1024, 4096, 4096, 3072, MN2);
    combine2<<<MN2 / 1024, 256>>>(part, x, rh, MN2, 4);

    // GEMM3: out = ...   M=256, N=4096, K=3072, z=3 (Kper=1024) -> 192 CTAs
    gemm_part<<<dim3(4096 / 128, 2, 3), 256>>>(
        rh, B1, part, 1024, 3072, 9216, 4096, MN1);
    combine3<<<MN1 / 1024, 256>>>(part, a0f, smp, out, MN1, 3);
}

// round 16
// speedup vs baseline: 1.1139x; 1.1139x over previous
#include <cuda_runtime.h>
#include <cuda_bf16.h>
#include <cuda_fp8.h>
#include <cstdint>

// Math (first-order collapse of 19 gradient steps, validated):
//   a0    = x @ phi
//   resid = a0 @ phi^T - x
//   out   = a0 - C19 * (resid @ phi + sm * sign(a0)),  C19 = 19*0.005/256
//
// R16: legacy mma.sync on sm_100 is instruction-rate-throttled (~28 cyc/MMA/SMSP
// measured invariant across R7-R15). Use fp8 m16n8k32 (4096 MAC/instr, 2x bf16)
// for GEMM2+GEMM3 (correction terms tolerate e4m3). GEMM1 stays bf16 hi/lo
// K-concat split (K=9216): A1=[xh|xh|xl], B1=[phT|plT|phT].
// Scales: phi x16, a0 x16, resid x8 (e4m3 normal range; satfinite).

#define DINL __device__ __forceinline__

constexpr float SP = 16.0f;   // phi scale
constexpr float SA = 16.0f;   // a0 scale
constexpr float SR = 8.0f;    // resid scale

// ---------------- scratch (device globals; no allocation allowed) -----------
__device__ __align__(1024) __nv_bfloat16 g_A1[256 * 9216];   // 4.7 MB
__device__ __align__(1024) __nv_bfloat16 g_B1[4096 * 9216];  // 75.5 MB
__device__ __align__(1024) float         g_a0f[256 * 4096];  // 4.2 MB
__device__ __align__(1024) uint8_t       g_a08[256 * 4096];  // 1.0 MB  fp8(SA*a0)
__device__ __align__(1024) uint8_t       g_rh8[256 * 3072];  // 0.8 MB  fp8(SR*resid)
__device__ __align__(1024) uint8_t       g_B2f8[3072 * 4096]; // 12.6 MB fp8(SP*phi) [pix][neu]
__device__ __align__(1024) uint8_t       g_B3f8[4096 * 3072]; // 12.6 MB fp8(SP*phi) [neu][pix]

// ---------------- PTX helpers -----------------------------------------------
DINL uint32_t smem_u32(const void* p) {
    uint32_t a;
    asm("{ .reg .u64 t; cvta.to.shared.u64 t, %1; cvt.u32.u64 %0, t; }"
        : "=r"(a) : "l"(p));
    return a;
}

#define CP16(dst, src) \
    asm volatile("cp.async.cg.shared.global [%0], [%1], 16;" :: "r"(dst), "l"(src) : "memory")
#define CP_COMMIT() asm volatile("cp.async.commit_group;" ::: "memory")
#define CP_WAIT2()  asm volatile("cp.async.wait_group 2;" ::: "memory")

#define LDSM4(r0, r1, r2, r3, addr) \
    asm volatile("ldmatrix.sync.aligned.m8n8.x4.shared.b16 {%0,%1,%2,%3}, [%4];" \
        : "=r"(r0), "=r"(r1), "=r"(r2), "=r"(r3) : "r"(addr))

DINL void mma_bf16(float& d0, float& d1, float& d2, float& d3,
                   uint32_t a0, uint32_t a1, uint32_t a2, uint32_t a3,
                   uint32_t b0, uint32_t b1) {
    asm volatile(
        "mma.sync.aligned.m16n8k16.row.col.f32.bf16.bf16.f32 "
        "{%0,%1,%2,%3}, {%4,%5,%6,%7}, {%8,%9}, {%0,%1,%2,%3};"
        : "+f"(d0), "+f"(d1), "+f"(d2), "+f"(d3)
        : "r"(a0), "r"(a1), "r"(a2), "r"(a3), "r"(b0), "r"(b1));
}

DINL void mma_fp8(float& d0, float& d1, float& d2, float& d3,
                  uint32_t a0, uint32_t a1, uint32_t a2, uint32_t a3,
                  uint32_t b0, uint32_t b1) {
    asm volatile(
        "mma.sync.aligned.m16n8k32.row.col.f32.e4m3.e4m3.f32 "
        "{%0,%1,%2,%3}, {%4,%5,%6,%7}, {%8,%9}, {%0,%1,%2,%3};"
        : "+f"(d0), "+f"(d1), "+f"(d2), "+f"(d3)
        : "r"(a0), "r"(a1), "r"(a2), "r"(a3), "r"(b0), "r"(b1));
}

DINL uint16_t packf8(float a, float b) {
    return (uint16_t)__nv_cvt_float2_to_fp8x2(make_float2(a, b),
                                              __NV_SATFINITE, __NV_E4M3);
}

// ---------------- conversion kernels -----------------------------------------
__global__ __launch_bounds__(256) void conv_x(const float* __restrict__ x,
                                              __nv_bfloat16* __restrict__ A1) {
    int t = blockIdx.x * 256 + threadIdx.x;  // 256*3072 elements
    int m = t / 3072;
    int k = t - m * 3072;
    float f = x[t];
    __nv_bfloat16 h = __float2bfloat16(f);
    __nv_bfloat16 l = __float2bfloat16(f - __bfloat162float(h));
    size_t base = (size_t)m * 9216 + k;
    A1[base] = h;          // pairs with phT
    A1[base + 3072] = h;   // pairs with plT
    A1[base + 6144] = l;   // pairs with phT
}

// tile: 64 pixels (p) x 32 neurons (n), 512 threads
__global__ __launch_bounds__(512) void conv_phi(const float* __restrict__ phi,
                                                __nv_bfloat16* __restrict__ B1,
                                                uint8_t* __restrict__ B2f8,
                                                uint8_t* __restrict__ B3f8) {
    __shared__ float tile[64][33];
    int p0 = blockIdx.y * 64, n0 = blockIdx.x * 32;
    int tx = threadIdx.x & 31, ty = threadIdx.x >> 5;  // ty 0..15
#pragma unroll
    for (int r = 0; r < 4; r++) {
        int pl = ty + 16 * r;
        float f = phi[(size_t)(p0 + pl) * 4096 + n0 + tx];
        tile[pl][tx] = f;
        // GEMM2 B: rows = pixel, K = neuron
        uint16_t v = packf8(SP * f, 0.0f);
        B2f8[(size_t)(p0 + pl) * 4096 + n0 + tx] = (uint8_t)(v & 0xFF);
    }
    __syncthreads();
    int pl2 = threadIdx.x & 63, nl2 = threadIdx.x >> 6;  // nl2 0..7
#pragma unroll
    for (int r = 0; r < 4; r++) {
        int nl = nl2 + 8 * r;
        float f = tile[pl2][nl];
        __nv_bfloat16 h = __float2bfloat16(f);
        __nv_bfloat16 l = __float2bfloat16(f - __bfloat162float(h));
        size_t base = (size_t)(n0 + nl) * 9216 + p0 + pl2;
        B1[base] = h;          // phT
        B1[base + 3072] = l;   // plT
        B1[base + 6144] = h;   // phT (pairs with xl)
        // GEMM3 B: rows = neuron, K = pixel
        uint16_t v = packf8(SP * f, 0.0f);
        B3f8[(size_t)(n0 + nl) * 3072 + p0 + pl2] = (uint8_t)(v & 0xFF);
    }
}

// ---------------- GEMM common ------------------------------------------------
// BM=64, BN=64; row data = 64 B (bf16: BK=32 elems / fp8: BK=64 elems).
// 128 threads = 4 warps (2M x 2N); warp tile 32x32.
// 4-stage cp.async ring, prefetch distance 3, ONE __syncthreads per iter,
// commit every iteration (group index == tile index; R12 discipline).

constexpr int SAu = 20;             // u32 row stride (16 data + 4 pad)
constexpr int STG = 64 * SAu;       // 1280 u32 per operand per stage

// GEMM1 (bf16): a0f = A1 @ B1^T (fp32) + a08 = fp8(SA * a0)
__global__ __launch_bounds__(128) void gemm1_bf16(
    const __nv_bfloat16* __restrict__ A, const __nv_bfloat16* __restrict__ B,
    float* __restrict__ Cf, uint8_t* __restrict__ C8,
    int K, int lda, int ldb, int ldc)
{
    __shared__ uint32_t As[4 * STG];
    __shared__ uint32_t Bs[4 * STG];
    const uint32_t sA_u = smem_u32(As);
    const uint32_t sB_u = smem_u32(Bs);

    const int tid = threadIdx.x, lane = tid & 31, wid = tid >> 5;
    const int wm = wid >> 1, wn = wid & 1;
    const int m0 = blockIdx.y * 64, n0 = blockIdx.x * 64;
    const int g = lane >> 2, c4 = lane & 3;
    const int j = lane >> 3, r8 = lane & 7;
    const uint32_t aoffB = (uint32_t)(((j & 1) * 8 + r8) * SAu + (j >> 1) * 4) * 4;
    const uint32_t boffB = (uint32_t)(r8 * SAu + (j & 1) * 4 + (j >> 1) * 8) * 4;

    float acc[2][4][4];
#pragma unroll
    for (int mt = 0; mt < 2; mt++)
#pragma unroll
        for (int nt = 0; nt < 4; nt++)
#pragma unroll
            for (int r = 0; r < 4; r++) acc[mt][nt][r] = 0.0f;

    const int nk = K >> 5;   // BK = 32 bf16

    auto load_tile = [&](int t, int slot) {
        const char* Ab = (const char*)A + ((size_t)m0 * lda + t * 32) * 2;
        uint32_t ad = sA_u + slot * STG * 4;
#pragma unroll
        for (int h = 0; h < 2; h++) {
            int idx = tid + h * 128;
            int row = idx >> 2, seg = idx & 3;
            CP16(ad + (uint32_t)(row * SAu + seg * 4) * 4,
                 Ab + (size_t)row * lda * 2 + seg * 16);
        }
        const char* Bb = (const char*)B + ((size_t)n0 * ldb + t * 32) * 2;
        uint32_t bd = sB_u + slot * STG * 4;
#pragma unroll
        for (int h = 0; h < 2; h++) {
            int idx = tid + h * 128;
            int row = idx >> 2, seg = idx & 3;
            CP16(bd + (uint32_t)(row * SAu + seg * 4) * 4,
                 Bb + (size_t)row * ldb * 2 + seg * 16);
        }
    };

    load_tile(0, 0); CP_COMMIT();
    load_tile(1, 1); CP_COMMIT();
    load_tile(2, 2); CP_COMMIT();

    for (int i = 0; i < nk; i++) {
        CP_WAIT2();
        __syncthreads();
        if (i + 3 < nk) load_tile(i + 3, (i + 3) & 3);
        CP_COMMIT();

        const uint32_t aBase = sA_u + ((i & 3) * STG + (wm * 32) * SAu) * 4 + aoffB;
        const uint32_t bBase = sB_u + ((i & 3) * STG + (wn * 32) * SAu) * 4 + boffB;

        uint32_t bb[4][2][2];
#pragma unroll
        for (int nt = 0; nt < 4; nt++) {
            uint32_t ba = bBase + (uint32_t)(nt * 8 * SAu) * 4;
            LDSM4(bb[nt][0][0], bb[nt][0][1], bb[nt][1][0], bb[nt][1][1], ba);
        }
#pragma unroll
        for (int ks = 0; ks < 2; ks++) {
            uint32_t aa[2][4];
#pragma unroll
            for (int mt = 0; mt < 2; mt++) {
                uint32_t aaddr = aBase + (uint32_t)(mt * 16 * SAu + ks * 8) * 4;
                LDSM4(aa[mt][0], aa[mt][1], aa[mt][2], aa[mt][3], aaddr);
            }
#pragma unroll
            for (int mt = 0; mt < 2; mt++)
#pragma unroll
                for (int nt = 0; nt < 4; nt++)
                    mma_bf16(acc[mt][nt][0], acc[mt][nt][1], acc[mt][nt][2], acc[mt][nt][3],
                             aa[mt][0], aa[mt][1], aa[mt][2], aa[mt][3],
                             bb[nt][ks][0], bb[nt][ks][1]);
        }
    }

#pragma unroll
    for (int mt = 0; mt < 2; mt++) {
        const int r0 = m0 + wm * 32 + mt * 16 + g;
#pragma unroll
        for (int nt = 0; nt < 4; nt++) {
            const int col = n0 + wn * 32 + nt * 8 + 2 * c4;
#pragma unroll
            for (int half = 0; half < 2; half++) {
                const int row = r0 + half * 8;
                const float d0 = acc[mt][nt][half * 2 + 0];
                const float d1 = acc[mt][nt][half * 2 + 1];
                const size_t idx = (size_t)row * ldc + col;
                float2 v = {d0, d1};
                *reinterpret_cast<float2*>(&Cf[idx]) = v;
                *reinterpret_cast<uint16_t*>(&C8[idx]) = packf8(SA * d0, SA * d1);
            }
        }
    }
}

// fp8 GEMM (m16n8k32): MODE 1: rh8 = fp8(SR*(acc/(SA*SP) - X))
//                      MODE 2: out = A0 - c19*(acc/(SR*SP) + sm*sign(A0))
template <int MODE>
__global__ __launch_bounds__(128) void gemm_fp8(
    const uint8_t* __restrict__ A, const uint8_t* __restrict__ B,
    const float* __restrict__ X, const float* __restrict__ A0,
    const float* __restrict__ SMP, float* __restrict__ Cf,
    uint8_t* __restrict__ C8, int K, int lda, int ldb, int ldc)
{
    __shared__ uint32_t As[4 * STG];
    __shared__ uint32_t Bs[4 * STG];
    const uint32_t sA_u = smem_u32(As);
    const uint32_t sB_u = smem_u32(Bs);

    const int tid = threadIdx.x, lane = tid & 31, wid = tid >> 5;
    const int wm = wid >> 1, wn = wid & 1;
    const int m0 = blockIdx.y * 64, n0 = blockIdx.x * 64;
    const int g = lane >> 2, c4 = lane & 3;
    const int j = lane >> 3, r8 = lane & 7;
    // byte-identical to bf16 offsets: 64B rows, j selects row+8 / +16B chunk
    const uint32_t aoffB = (uint32_t)(((j & 1) * 8 + r8) * SAu + (j >> 1) * 4) * 4;
    const uint32_t boffB = (uint32_t)(r8 * SAu + (j & 1) * 4 + (j >> 1) * 8) * 4;

    float acc[2][4][4];
#pragma unroll
    for (int mt = 0; mt < 2; mt++)
#pragma unroll
        for (int nt = 0; nt < 4; nt++)
#pragma unroll
            for (int r = 0; r < 4; r++) acc[mt][nt][r] = 0.0f;

    const int nk = K >> 6;   // BK = 64 fp8 elements = 64 B

    auto load_tile = [&](int t, int slot) {
        const char* Ab = (const char*)A + (size_t)m0 * lda + t * 64;
        uint32_t ad = sA_u + slot * STG * 4;
#pragma unroll
        for (int h = 0; h < 2; h++) {
            int idx = tid + h * 128;
            int row = idx >> 2, seg = idx & 3;
            CP16(ad + (uint32_t)(row * SAu + seg * 4) * 4,
                 Ab + (size_t)row * lda + seg * 16);
        }
        const char* Bb = (const char*)B + (size_t)n0 * ldb + t * 64;
        uint32_t bd = sB_u + slot * STG * 4;
#pragma unroll
        for (int h = 0; h < 2; h++) {
            int idx = tid + h * 128;
            int row = idx >> 2, seg = idx & 3;
            CP16(bd + (uint32_t)(row * SAu + seg * 4) * 4,
                 Bb + (size_t)row * ldb + seg * 16);
        }
    };

    load_tile(0, 0); CP_COMMIT();
    load_tile(1, 1); CP_COMMIT();
    load_tile(2, 2); CP_COMMIT();

    for (int i = 0; i < nk; i++) {
        CP_WAIT2();
        __syncthreads();
        if (i + 3 < nk) load_tile(i + 3, (i + 3) & 3);
        CP_COMMIT();

        const uint32_t aBase = sA_u + ((i & 3) * STG + (wm * 32) * SAu) * 4 + aoffB;
        const uint32_t bBase = sB_u + ((i & 3) * STG + (wn * 32) * SAu) * 4 + boffB;

        // B: x4 j0..j3 = (b0, b1) of n-rows r8 and r8+... j2,j3 = k bytes 32-63
        // = second k32 step for same n-tile. One x4 per nt covers both k32 steps.
        uint32_t bb[4][2][2];   // [nt][ks32][2]
#pragma unroll
        for (int nt = 0; nt < 4; nt++) {
            uint32_t ba = bBase + (uint32_t)(nt * 8 * SAu) * 4;
            LDSM4(bb[nt][0][0], bb[nt][0][1], bb[nt][1][0], bb[nt][1][1], ba);
        }
#pragma unroll
        for (int ks = 0; ks < 2; ks++) {
            uint32_t aa[2][4];
#pragma unroll
            for (int mt = 0; mt < 2; mt++) {
                uint32_t aaddr = aBase + (uint32_t)(mt * 16 * SAu + ks * 8) * 4;
                LDSM4(aa[mt][0], aa[mt][1], aa[mt][2], aa[mt][3], aaddr);
            }
#pragma unroll
            for (int mt = 0; mt < 2; mt++)
#pragma unroll
                for (int nt = 0; nt < 4; nt++)
                    mma_fp8(acc[mt][nt][0], acc[mt][nt][1], acc[mt][nt][2], acc[mt][nt][3],
                            aa[mt][0], aa[mt][1], aa[mt][2], aa[mt][3],
                            bb[nt][ks][0], bb[nt][ks][1]);
        }
    }

    const float c19 = 19.0f * (0.005f / 256.0f);
    const float inv_ap = 1.0f / (SA * SP);
    const float inv_rp = 1.0f / (SR * SP);
    const float smv = (MODE == 2) ? SMP[0] : 0.0f;
#pragma unroll
    for (int mt = 0; mt < 2; mt++) {
        const int r0 = m0 + wm * 32 + mt * 16 + g;
#pragma unroll
        for (int nt = 0; nt < 4; nt++) {
            const int col = n0 + wn * 32 + nt * 8 + 2 * c4;
#pragma unroll
            for (int half = 0; half < 2; half++) {
                const int row = r0 + half * 8;
                const float d0 = acc[mt][nt][half * 2 + 0];
                const float d1 = acc[mt][nt][half * 2 + 1];
                const size_t idx = (size_t)row * ldc + col;
                if (MODE == 1) {
                    float2 xv = *reinterpret_cast<const float2*>(&X[idx]);
                    float r0f = d0 * inv_ap - xv.x;
                    float r1f = d1 * inv_ap - xv.y;
                    *reinterpret_cast<uint16_t*>(&C8[idx]) = packf8(SR * r0f, SR * r1f);
                } else {
                    float2 av = *reinterpret_cast<const float2*>(&A0[idx]);
                    float s0 = (av.x > 0.f) ? 1.f : ((av.x < 0.f) ? -1.f : 0.f);
                    float s1 = (av.y > 0.f) ? 1.f : ((av.y < 0.f) ? -1.f : 0.f);
                    float2 v = {av.x - c19 * (d0 * inv_rp + smv * s0),
                                av.y - c19 * (d1 * inv_rp + smv * s1)};
                    *reinterpret_cast<float2*>(&Cf[idx]) = v;
                }
            }
        }
    }
}

// ---------------- launch -----------------------------------------------------
extern "C" void kernel_launch(void* const* d_in, const int* in_sizes, int n_in,
                              void* d_out, int out_size)
{
    const float* x   = (const float*)d_in[0];  // [256, 3072]
    const float* phi = (const float*)d_in[1];  // [3072, 4096]
    const float* smp = (const float*)d_in[2];  // scalar
    float* out = (float*)d_out;                // [256, 4096]

    __nv_bfloat16 *A1, *B1;
    float *a0f;
    uint8_t *a08, *rh8, *B2f8, *B3f8;
    cudaGetSymbolAddress((void**)&A1, g_A1);
    cudaGetSymbolAddress((void**)&B1, g_B1);
    cudaGetSymbolAddress((void**)&a0f, g_a0f);
    cudaGetSymbolAddress((void**)&a08, g_a08);
    cudaGetSymbolAddress((void**)&rh8, g_rh8);
    cudaGetSymbolAddress((void**)&B2f8, g_B2f8);
    cudaGetSymbolAddress((void**)&B3f8, g_B3f8);

    // conversions
    conv_x<<<(256 * 3072) / 256, 256>>>(x, A1);
    conv_phi<<<dim3(4096 / 32, 3072 / 64), 512>>>(phi, B1, B2f8, B3f8);

    // GEMM1 (bf16 split): a0 = A1 @ B1^T   M=256, N=4096, K=9216
    gemm1_bf16<<<dim3(4096 / 64, 4), 128>>>(
        A1, B1, a0f, a08, 9216, 9216, 9216, 4096);

    // GEMM2 (fp8): resid = a08 @ B2f8^T / (SA*SP) - x   M=256, N=3072, K=4096
    gemm_fp8<1><<<dim3(3072 / 64, 4), 128>>>(
        a08, B2f8, x, nullptr, smp, nullptr, rh8, 4096, 4096, 4096, 3072);

    // GEMM3 (fp8): out = a0f - c19*(rh8 @ B3f8^T/(SR*SP) + sm*sign(a0f))
    //              M=256, N=4096, K=3072
    gemm_fp8<2><<<dim3(4096 / 64, 4), 128>>>(
        rh8, B3f8, nullptr, a0f, smp, out, nullptr, 3072, 3072, 3072, 4096);
}